// round 15
// baseline (speedup 1.0000x reference)
#include <cuda_runtime.h>
#include <cuda_bf16.h>
#include <cuda_fp16.h>
#include <math.h>
#include <stdint.h>

#define Bc 4
#define Lc 4096
#define Hc 16
#define Dc 128
#define BHc 64
#define SPLITQ 32
#define KVS 2
#define EPSc 1e-6f

// ---------------- device scratch ----------------
__device__ float g_qpart[Bc * SPLITQ * Hc * Dc];
__device__ float g_alpha[BHc * Lc];          // RAW scores (softmax folded into k4)
__device__ float g_kvpart[(size_t)KVS * BHc * Dc * Dc];
__device__ float g_ksumpart[KVS * BHc * Dc];

// ---------------- helpers ----------------
__device__ __forceinline__ uint32_t smem_u32(const void* p) {
    uint32_t a;
    asm("{ .reg .u64 t; cvta.to.shared.u64 t, %1; cvt.u32.u64 %0, t; }" : "=r"(a) : "l"(p));
    return a;
}
__device__ __forceinline__ void ldsm_x4(uint32_t r[4], uint32_t addr) {
    asm volatile("ldmatrix.sync.aligned.m8n8.x4.shared.b16 {%0,%1,%2,%3}, [%4];"
                 : "=r"(r[0]), "=r"(r[1]), "=r"(r[2]), "=r"(r[3]) : "r"(addr));
}
__device__ __forceinline__ void ldsm_x4_t(uint32_t r[4], uint32_t addr) {
    asm volatile("ldmatrix.sync.aligned.m8n8.x4.trans.shared.b16 {%0,%1,%2,%3}, [%4];"
                 : "=r"(r[0]), "=r"(r[1]), "=r"(r[2]), "=r"(r[3]) : "r"(addr));
}
__device__ __forceinline__ void mma16816h(float c[4], const uint32_t a[4], uint32_t b0, uint32_t b1) {
    asm volatile(
        "mma.sync.aligned.m16n8k16.row.col.f32.f16.f16.f32 "
        "{%0,%1,%2,%3}, {%4,%5,%6,%7}, {%8,%9}, {%0,%1,%2,%3};"
        : "+f"(c[0]), "+f"(c[1]), "+f"(c[2]), "+f"(c[3])
        : "r"(a[0]), "r"(a[1]), "r"(a[2]), "r"(a[3]), "r"(b0), "r"(b1));
}
__device__ __forceinline__ uint32_t pack_h2(__half a, __half b) {
    __half2 t;
    t.x = a; t.y = b;
    return *reinterpret_cast<uint32_t*>(&t);
}
__device__ __forceinline__ void split4h(float4 v, uint2& hi, uint2& lo) {
    __half h0 = __float2half_rn(v.x), h1 = __float2half_rn(v.y);
    __half h2 = __float2half_rn(v.z), h3 = __float2half_rn(v.w);
    __half l0 = __float2half_rn(v.x - __half2float(h0));
    __half l1 = __float2half_rn(v.y - __half2float(h1));
    __half l2 = __float2half_rn(v.z - __half2float(h2));
    __half l3 = __float2half_rn(v.w - __half2float(h3));
    hi.x = pack_h2(h0, h1); hi.y = pack_h2(h2, h3);
    lo.x = pack_h2(l0, l1); lo.y = pack_h2(l2, l3);
}
__device__ __forceinline__ void cvt4h(float4 v, uint2& hi) {
    hi.x = pack_h2(__float2half_rn(v.x), __float2half_rn(v.y));
    hi.y = pack_h2(__float2half_rn(v.z), __float2half_rn(v.w));
}

// ================= K1: partial sum of Q over L (contiguous float4 streaming) =================
__global__ void __launch_bounds__(512) k1_qpart(const float* __restrict__ Q) {
    int b = blockIdx.x, s = blockIdx.y, t = threadIdx.x;
    const float4* p = (const float4*)(Q + ((size_t)b * Lc + s * (Lc / SPLITQ)) * Hc * Dc) + t;
    float4 acc = make_float4(0.f, 0.f, 0.f, 0.f);
#pragma unroll 8
    for (int i = 0; i < Lc / SPLITQ; i++) {
        float4 v = p[(size_t)i * 512];
        acc.x += v.x; acc.y += v.y; acc.z += v.z; acc.w += v.w;
    }
    *(float4*)(g_qpart + (size_t)(b * SPLITQ + s) * (Hc * Dc) + t * 4) = acc;
}

// ================= K2: raw scores (q_global folded in) =================
__global__ void k2_scores(const float* __restrict__ K) {
    __shared__ float qg[Dc];
    int bh = blockIdx.x;
    int b = bh >> 4, h = bh & 15;
    int t = threadIdx.x, warp = t >> 5, lane = t & 31;
    if (t < Dc) {
        float acc = 0.f;
#pragma unroll
        for (int s = 0; s < SPLITQ; s++)
            acc += g_qpart[((b * SPLITQ + s) * Hc + h) * Dc + t];
        qg[t] = acc * (1.0f / ((float)Lc * sqrtf(2048.0f)));
    }
    __syncthreads();
    float4 q = *(const float4*)&qg[lane * 4];
    int l0 = blockIdx.y * 256 + warp * 32;
#pragma unroll 4
    for (int i = 0; i < 32; i++) {
        int l = l0 + i;
        const float4 kk = *(const float4*)(K + ((size_t)(b * Lc + l) * Hc + h) * Dc + lane * 4);
        float p = q.x * kk.x + q.y * kk.y + q.z * kk.z + q.w * kk.w;
        p += __shfl_xor_sync(0xFFFFFFFFu, p, 16);
        p += __shfl_xor_sync(0xFFFFFFFFu, p, 8);
        p += __shfl_xor_sync(0xFFFFFFFFu, p, 4);
        p += __shfl_xor_sync(0xFFFFFFFFu, p, 2);
        p += __shfl_xor_sync(0xFFFFFFFFu, p, 1);
        if (lane == 0) g_alpha[bh * Lc + l] = p;
    }
}

// ================= k4: KVT[e][d] = sum_l V[l][e]*(alpha*phiK)[l][d] =================
// (unchanged from R14) fp16 2-pass, grid (BHc, KVS=2), 512 threads, 4x4 m32 x n32.
// Softmax folded into prologue. 64-row chunks, double-buffered, register-staged loads.
#define T_KHI 0
#define T_KLO 16384
#define T_VHI 32768
#define K4_BUF 49152
#define K4_KS  98304
#define K4_ALPHA 106496
#define K4_SMEM (106496 + 8192)

__global__ void __launch_bounds__(512) k4_mma(const float* __restrict__ phiK,
                                              const float* __restrict__ V) {
    extern __shared__ __align__(16) char smem[];
    uint32_t sb = smem_u32(smem);
    int bh = blockIdx.x, s = blockIdx.y;
    int b = bh >> 4, h = bh & 15;
    int t = threadIdx.x, lane = t & 31, w = t >> 5;
    float* alpha_s = (float*)(smem + K4_ALPHA);
    float* red = (float*)(smem + K4_KS);

    // ---- prologue: softmax over full L (deterministic, redundant per block) ----
    {
        float v[8];
#pragma unroll
        for (int i = 0; i < 8; i++) v[i] = g_alpha[bh * Lc + t + i * 512];
        float m = v[0];
#pragma unroll
        for (int i = 1; i < 8; i++) m = fmaxf(m, v[i]);
        red[t] = m;
        __syncthreads();
        for (int st = 256; st > 0; st >>= 1) {
            if (t < st) red[t] = fmaxf(red[t], red[t + st]);
            __syncthreads();
        }
        m = red[0];
        __syncthreads();
        float sum = 0.f;
#pragma unroll
        for (int i = 0; i < 8; i++) { v[i] = expf(v[i] - m); sum += v[i]; }
        red[t] = sum;
        __syncthreads();
        for (int st = 256; st > 0; st >>= 1) {
            if (t < st) red[t] += red[t + st];
            __syncthreads();
        }
        float scale = (float)Lc / red[0];
#pragma unroll
        for (int i = 0; i < 4; i++) alpha_s[t + i * 512] = v[s * 4 + i] * scale;
        __syncthreads();
    }

    float acc[8][4];
#pragma unroll
    for (int i = 0; i < 8; i++)
#pragma unroll
        for (int j = 0; j < 4; j++) acc[i][j] = 0.f;
    float4 ksum4 = make_float4(0.f, 0.f, 0.f, 0.f);

    const int c4 = lane;
    const int NCH = (Lc / KVS) / 64;   // 32

    float4 kvst[4], vvst[4];
    float ast[4];

    auto STAGE = [&](int chunk) {
        int l0 = s * (Lc / KVS) + chunk * 64;
#pragma unroll
        for (int i = 0; i < 4; i++) {
            int lr = w + 16 * i;
            int l = l0 + lr;
            size_t off = ((size_t)(b * Lc + l) * Hc + h) * Dc + c4 * 4;
            ast[i] = alpha_s[chunk * 64 + lr];
            kvst[i] = *(const float4*)(phiK + off);
            vvst[i] = *(const float4*)(V + off);
        }
    };
    auto CVTST = [&](int buf) {
        uint32_t base = (uint32_t)(buf * K4_BUF);
#pragma unroll
        for (int i = 0; i < 4; i++) {
            int lr = w + 16 * i;
            float a = ast[i];
            float4 kv = kvst[i];
            kv.x *= a; kv.y *= a; kv.z *= a; kv.w *= a;
            ksum4.x += kv.x; ksum4.y += kv.y; ksum4.z += kv.z; ksum4.w += kv.w;
            uint32_t wo = lr * 256 + ((((uint32_t)(c4 >> 1)) ^ (lr & 7)) << 4) + (c4 & 1) * 8;
            uint2 hi, lo;
            split4h(kv, hi, lo);
            *(uint2*)(smem + base + T_KHI + wo) = hi;
            *(uint2*)(smem + base + T_KLO + wo) = lo;
            cvt4h(vvst[i], hi);
            *(uint2*)(smem + base + T_VHI + wo) = hi;
        }
    };

    const int ms = w & 3, nh = w >> 2;   // 4x4 warp grid
    const int matj = lane >> 3, rr = lane & 7;
    auto MMA = [&](int buf) {
        uint32_t base = sb + (uint32_t)(buf * K4_BUF);
#pragma unroll
        for (int ks = 0; ks < 4; ks++) {
            int lb = ks * 16;
            uint32_t ah[2][4];
            int lA = lb + (matj >> 1) * 8 + rr;
#pragma unroll
            for (int mi = 0; mi < 2; mi++) {
                int mt = ms * 2 + mi;
                uint32_t aoff = lA * 256 + ((((uint32_t)(mt * 2 + (matj & 1))) ^ (lA & 7)) << 4);
                ldsm_x4_t(ah[mi], base + T_VHI + aoff);
            }
            int lB = lb + (matj & 1) * 8 + rr;
            uint32_t brow = lB * 256;
#pragma unroll
            for (int ni = 0; ni < 2; ni++) {
                int nt = nh * 2 + ni;
                uint32_t boff = brow + ((((uint32_t)(nt * 2 + (matj >> 1))) ^ (lB & 7)) << 4);
                uint32_t bh4[4], bl4[4];
                ldsm_x4_t(bh4, base + T_KHI + boff);
                ldsm_x4_t(bl4, base + T_KLO + boff);
                int a0 = ni * 2, a1 = 4 + ni * 2;
                mma16816h(acc[a0],     ah[0], bh4[0], bh4[1]);
                mma16816h(acc[a0 + 1], ah[0], bh4[2], bh4[3]);
                mma16816h(acc[a1],     ah[1], bh4[0], bh4[1]);
                mma16816h(acc[a1 + 1], ah[1], bh4[2], bh4[3]);
                mma16816h(acc[a0],     ah[0], bl4[0], bl4[1]);
                mma16816h(acc[a0 + 1], ah[0], bl4[2], bl4[3]);
                mma16816h(acc[a1],     ah[1], bl4[0], bl4[1]);
                mma16816h(acc[a1 + 1], ah[1], bl4[2], bl4[3]);
            }
        }
    };

    STAGE(0);
    CVTST(0);
    for (int c = 0; c < NCH; c++) {
        __syncthreads();
        if (c + 1 < NCH) STAGE(c + 1);
        MMA(c & 1);
        if (c + 1 < NCH) CVTST((c + 1) & 1);
    }

    __syncthreads();
    *(float4*)(smem + K4_KS + (w * 128 + c4 * 4) * 4) = ksum4;
    __syncthreads();
    if (t < 128) {
        float sum = 0.f;
        const float* ks_s = (const float*)(smem + K4_KS);
#pragma unroll
        for (int g = 0; g < 16; g++) sum += ks_s[g * 128 + t];
        g_ksumpart[(s * BHc + bh) * Dc + t] = sum;
    }

    int r_in = lane >> 2;
    int cc_in = 2 * (lane & 3);
#pragma unroll
    for (int mi = 0; mi < 2; mi++) {
#pragma unroll
        for (int ni = 0; ni < 2; ni++) {
#pragma unroll
            for (int half = 0; half < 2; half++) {
                const float* a = acc[mi * 4 + ni * 2 + half];
                int row = ms * 32 + mi * 16 + r_in;
                int col = nh * 32 + ni * 16 + half * 8 + cc_in;
                float* dst = g_kvpart + (((size_t)s * BHc + bh) * Dc + row) * Dc + col;
                *(float2*)(dst)          = make_float2(a[0], a[1]);
                *(float2*)(dst + 8 * Dc) = make_float2(a[2], a[3]);
            }
        }
    }
}

// ================= k5: out[l][e] = (phiQ_hi @ KVT^T) / (phiQ . ksum + eps) =================
// fp16 2-pass. grid (BHc, 4) = 256 blocks, 256 threads (8 warps, 2x4 grid, m32 x n32),
// 2 CTAs/SM. 16 tiles of 64 l-rows; B (KV hi+lo) resident 64KB; A double-buffered
// (2 x 16KB) with register-staged fill; denominator via shfl in the fill phase.
#define K5_A0   0
#define K5_ABUF 16384
#define K5_GHI  32768
#define K5_GLO  65536
#define K5_DEN  98304
#define K5_KS   98880
#define K5_SMEM (98880 + 512)

__global__ void __launch_bounds__(256, 2) k5_mma(const float* __restrict__ phiQ,
                                                 float* __restrict__ out) {
    extern __shared__ __align__(16) char smem[];
    uint32_t sb = smem_u32(smem);
    int bh = blockIdx.x, lt = blockIdx.y;
    int b = bh >> 4, h = bh & 15;
    int l0 = lt * (Lc / 4);
    int t = threadIdx.x, lane = t & 31, w = t >> 5;
    float* den_s = (float*)(smem + K5_DEN);
    float* ks_s = (float*)(smem + K5_KS);

    // ---- B fill: reduce KVS=2 fp32 partials, split to fp16 hi/lo ----
#pragma unroll
    for (int i = 0; i < 16; i++) {
        int seg = t + i * 256;          // 4096 float4 segments
        int e = seg >> 5, dq = seg & 31;
        size_t off = ((size_t)bh * Dc + e) * Dc + dq * 4;
        float4 p0 = *(const float4*)(g_kvpart + off);
        float4 p1 = *(const float4*)(g_kvpart + (size_t)(BHc * Dc) * Dc + off);
        p0.x += p1.x; p0.y += p1.y; p0.z += p1.z; p0.w += p1.w;
        uint2 hi, lo;
        split4h(p0, hi, lo);
        uint32_t wo = e * 256 + ((((uint32_t)(dq >> 1)) ^ (e & 7)) << 4) + (dq & 1) * 8;
        *(uint2*)(smem + K5_GHI + wo) = hi;
        *(uint2*)(smem + K5_GLO + wo) = lo;
    }
    if (t < 128) ks_s[t] = g_ksumpart[bh * Dc + t] + g_ksumpart[BHc * Dc + bh * Dc + t];
    __syncthreads();

    const int NT = (Lc / 4) / 64;   // 16 tiles of 64 rows
    const int c4 = lane;
    float4 ksq = *(const float4*)&ks_s[c4 * 4];

    float4 qst[8];
    auto STAGE = [&](int tile) {
        int l0t = l0 + tile * 64;
#pragma unroll
        for (int i = 0; i < 8; i++) {
            int lr = w + 8 * i;
            qst[i] = *(const float4*)(phiQ + ((size_t)(b * Lc + l0t + lr) * Hc + h) * Dc + c4 * 4);
        }
    };
    auto CVTST = [&](int buf) {
        uint32_t base = (uint32_t)(buf * K5_ABUF);
#pragma unroll
        for (int i = 0; i < 8; i++) {
            int lr = w + 8 * i;
            float4 q = qst[i];
            float part = q.x * ksq.x + q.y * ksq.y + q.z * ksq.z + q.w * ksq.w;
            part += __shfl_xor_sync(0xFFFFFFFFu, part, 16);
            part += __shfl_xor_sync(0xFFFFFFFFu, part, 8);
            part += __shfl_xor_sync(0xFFFFFFFFu, part, 4);
            part += __shfl_xor_sync(0xFFFFFFFFu, part, 2);
            part += __shfl_xor_sync(0xFFFFFFFFu, part, 1);
            if (lane == 0) den_s[buf * 64 + lr] = part;
            uint32_t wo = lr * 256 + ((((uint32_t)(c4 >> 1)) ^ (lr & 7)) << 4) + (c4 & 1) * 8;
            uint2 hi;
            cvt4h(q, hi);
            *(uint2*)(smem + base + K5_A0 + wo) = hi;
        }
    };

    const int ms = w & 1, nh = w >> 1;   // 2x4 warp grid (m64 x n128 block tile)
    const int matj = lane >> 3, rr = lane & 7;
    float acc[8][4];

    STAGE(0);
    CVTST(0);
    for (int tile = 0; tile < NT; tile++) {
        int buf = tile & 1;
#pragma unroll
        for (int i = 0; i < 8; i++)
#pragma unroll
            for (int j = 0; j < 4; j++) acc[i][j] = 0.f;
        __syncthreads();
        if (tile + 1 < NT) STAGE(tile + 1);

        uint32_t abase = sb + (uint32_t)(buf * K5_ABUF);
#pragma unroll
        for (int ks = 0; ks < 8; ks++) {
            uint32_t kbA = (uint32_t)(ks * 2 + (matj >> 1));
            uint32_t ah[2][4];
#pragma unroll
            for (int mi = 0; mi < 2; mi++) {
                int rowA = (ms * 2 + mi) * 16 + (matj & 1) * 8 + rr;
                uint32_t aoff = rowA * 256 + ((kbA ^ (rowA & 7)) << 4);
                ldsm_x4(ah[mi], abase + K5_A0 + aoff);
            }
            uint32_t kbB = (uint32_t)(ks * 2 + (matj & 1));
#pragma unroll
            for (int ni = 0; ni < 2; ni++) {
                int nt = nh * 2 + ni;
                int rowB = (nt * 2 + (matj >> 1)) * 8 + rr;
                uint32_t boff = rowB * 256 + ((kbB ^ (rowB & 7)) << 4);
                uint32_t bh4[4], bl4[4];
                ldsm_x4(bh4, sb + K5_GHI + boff);
                ldsm_x4(bl4, sb + K5_GLO + boff);
                int a0 = ni * 2, a1 = 4 + ni * 2;
                mma16816h(acc[a0],     ah[0], bh4[0], bh4[1]);
                mma16816h(acc[a0 + 1], ah[0], bh4[2], bh4[3]);
                mma16816h(acc[a1],     ah[1], bh4[0], bh4[1]);
                mma16816h(acc[a1 + 1], ah[1], bh4[2], bh4[3]);
                mma16816h(acc[a0],     ah[0], bl4[0], bl4[1]);
                mma16816h(acc[a0 + 1], ah[0], bl4[2], bl4[3]);
                mma16816h(acc[a1],     ah[1], bl4[0], bl4[1]);
                mma16816h(acc[a1 + 1], ah[1], bl4[2], bl4[3]);
            }
        }

        if (tile + 1 < NT) CVTST((tile + 1) & 1);

        // ---- epilogue (den_s[buf] stable until tile+2 writes it again) ----
        int r_in = lane >> 2;
        int cc_in = 2 * (lane & 3);
        int lb0 = l0 + tile * 64;
#pragma unroll
        for (int mi = 0; mi < 2; mi++) {
            int row = ms * 32 + mi * 16 + r_in;
            float i0 = 1.0f / (den_s[buf * 64 + row] + EPSc);
            float i1 = 1.0f / (den_s[buf * 64 + row + 8] + EPSc);
            float* o0 = out + ((size_t)(b * Lc + lb0 + row) * Hc + h) * Dc;
            float* o1 = o0 + (size_t)8 * Hc * Dc;
#pragma unroll
            for (int ni = 0; ni < 2; ni++) {
#pragma unroll
                for (int half = 0; half < 2; half++) {
                    const float* a = acc[mi * 4 + ni * 2 + half];
                    int col = nh * 32 + ni * 16 + half * 8 + cc_in;
                    *(float2*)(o0 + col) = make_float2(a[0] * i0, a[1] * i0);
                    *(float2*)(o1 + col) = make_float2(a[2] * i1, a[3] * i1);
                }
            }
        }
    }
}

// ================= launcher =================
extern "C" void kernel_launch(void* const* d_in, const int* in_sizes, int n_in,
                              void* d_out, int out_size) {
    const float* Q    = (const float*)d_in[0];
    const float* K    = (const float*)d_in[1];
    const float* V    = (const float*)d_in[2];
    const float* phiQ = (const float*)d_in[3];
    const float* phiK = (const float*)d_in[4];
    float* out = (float*)d_out;

    cudaFuncSetAttribute(k4_mma, cudaFuncAttributeMaxDynamicSharedMemorySize, K4_SMEM);
    cudaFuncSetAttribute(k5_mma, cudaFuncAttributeMaxDynamicSharedMemorySize, K5_SMEM);

    k1_qpart<<<dim3(Bc, SPLITQ), 512>>>(Q);
    k2_scores<<<dim3(BHc, Lc / 256), 256>>>(K);
    k4_mma<<<dim3(BHc, KVS), 512, K4_SMEM>>>(phiK, V);
    k5_mma<<<dim3(BHc, 4), 256, K5_SMEM>>>(phiQ, out);
}

// round 16
// speedup vs baseline: 1.0616x; 1.0616x over previous
#include <cuda_runtime.h>
#include <cuda_bf16.h>
#include <cuda_fp16.h>
#include <math.h>
#include <stdint.h>

#define Bc 4
#define Lc 4096
#define Hc 16
#define Dc 128
#define BHc 64
#define SPLITQ 32
#define KVS 2
#define EPSc 1e-6f

// ---------------- device scratch ----------------
__device__ float g_qpart[Bc * SPLITQ * Hc * Dc];
__device__ float g_alpha[BHc * Lc];          // RAW scores (softmax folded into k4)
__device__ float g_kvpart[(size_t)KVS * BHc * Dc * Dc];
__device__ float g_ksumpart[KVS * BHc * Dc];

// ---------------- helpers ----------------
__device__ __forceinline__ uint32_t smem_u32(const void* p) {
    uint32_t a;
    asm("{ .reg .u64 t; cvta.to.shared.u64 t, %1; cvt.u32.u64 %0, t; }" : "=r"(a) : "l"(p));
    return a;
}
__device__ __forceinline__ void ldsm_x4(uint32_t r[4], uint32_t addr) {
    asm volatile("ldmatrix.sync.aligned.m8n8.x4.shared.b16 {%0,%1,%2,%3}, [%4];"
                 : "=r"(r[0]), "=r"(r[1]), "=r"(r[2]), "=r"(r[3]) : "r"(addr));
}
__device__ __forceinline__ void ldsm_x4_t(uint32_t r[4], uint32_t addr) {
    asm volatile("ldmatrix.sync.aligned.m8n8.x4.trans.shared.b16 {%0,%1,%2,%3}, [%4];"
                 : "=r"(r[0]), "=r"(r[1]), "=r"(r[2]), "=r"(r[3]) : "r"(addr));
}
__device__ __forceinline__ void mma16816h(float c[4], const uint32_t a[4], uint32_t b0, uint32_t b1) {
    asm volatile(
        "mma.sync.aligned.m16n8k16.row.col.f32.f16.f16.f32 "
        "{%0,%1,%2,%3}, {%4,%5,%6,%7}, {%8,%9}, {%0,%1,%2,%3};"
        : "+f"(c[0]), "+f"(c[1]), "+f"(c[2]), "+f"(c[3])
        : "r"(a[0]), "r"(a[1]), "r"(a[2]), "r"(a[3]), "r"(b0), "r"(b1));
}
__device__ __forceinline__ uint32_t pack_h2(__half a, __half b) {
    __half2 t;
    t.x = a; t.y = b;
    return *reinterpret_cast<uint32_t*>(&t);
}
__device__ __forceinline__ void split4h(float4 v, uint2& hi, uint2& lo) {
    __half h0 = __float2half_rn(v.x), h1 = __float2half_rn(v.y);
    __half h2 = __float2half_rn(v.z), h3 = __float2half_rn(v.w);
    __half l0 = __float2half_rn(v.x - __half2float(h0));
    __half l1 = __float2half_rn(v.y - __half2float(h1));
    __half l2 = __float2half_rn(v.z - __half2float(h2));
    __half l3 = __float2half_rn(v.w - __half2float(h3));
    hi.x = pack_h2(h0, h1); hi.y = pack_h2(h2, h3);
    lo.x = pack_h2(l0, l1); lo.y = pack_h2(l2, l3);
}
__device__ __forceinline__ void cvt4h(float4 v, uint2& hi) {
    hi.x = pack_h2(__float2half_rn(v.x), __float2half_rn(v.y));
    hi.y = pack_h2(__float2half_rn(v.z), __float2half_rn(v.w));
}

#define BAR_SYNC(id)   asm volatile("bar.sync %0, 512;"   :: "r"(id) : "memory")
#define BAR_ARRIVE(id) asm volatile("bar.arrive %0, 512;" :: "r"(id) : "memory")
#define GRID_DEP_SYNC() asm volatile("griddepcontrol.wait;" ::: "memory")
#define GRID_DEP_TRIGGER() asm volatile("griddepcontrol.launch_dependents;" ::: "memory")

// ================= K1: partial sum of Q over L (contiguous float4 streaming) =================
__global__ void __launch_bounds__(512) k1_qpart(const float* __restrict__ Q) {
    int b = blockIdx.x, s = blockIdx.y, t = threadIdx.x;
    const float4* p = (const float4*)(Q + ((size_t)b * Lc + s * (Lc / SPLITQ)) * Hc * Dc) + t;
    float4 acc = make_float4(0.f, 0.f, 0.f, 0.f);
#pragma unroll 8
    for (int i = 0; i < Lc / SPLITQ; i++) {
        float4 v = p[(size_t)i * 512];
        acc.x += v.x; acc.y += v.y; acc.z += v.z; acc.w += v.w;
    }
    *(float4*)(g_qpart + (size_t)(b * SPLITQ + s) * (Hc * Dc) + t * 4) = acc;
}

// ================= K2: raw scores (q_global folded in) =================
__global__ void k2_scores(const float* __restrict__ K) {
    __shared__ float qg[Dc];
    GRID_DEP_TRIGGER();   // let k4 launch early and prefetch phiK/V
    int bh = blockIdx.x;
    int b = bh >> 4, h = bh & 15;
    int t = threadIdx.x, warp = t >> 5, lane = t & 31;
    if (t < Dc) {
        float acc = 0.f;
#pragma unroll
        for (int s = 0; s < SPLITQ; s++)
            acc += g_qpart[((b * SPLITQ + s) * Hc + h) * Dc + t];
        qg[t] = acc * (1.0f / ((float)Lc * sqrtf(2048.0f)));
    }
    __syncthreads();
    float4 q = *(const float4*)&qg[lane * 4];
    int l0 = blockIdx.y * 256 + warp * 32;
#pragma unroll 4
    for (int i = 0; i < 32; i++) {
        int l = l0 + i;
        const float4 kk = *(const float4*)(K + ((size_t)(b * Lc + l) * Hc + h) * Dc + lane * 4);
        float p = q.x * kk.x + q.y * kk.y + q.z * kk.z + q.w * kk.w;
        p += __shfl_xor_sync(0xFFFFFFFFu, p, 16);
        p += __shfl_xor_sync(0xFFFFFFFFu, p, 8);
        p += __shfl_xor_sync(0xFFFFFFFFu, p, 4);
        p += __shfl_xor_sync(0xFFFFFFFFu, p, 2);
        p += __shfl_xor_sync(0xFFFFFFFFu, p, 1);
        if (lane == 0) g_alpha[bh * Lc + l] = p;
    }
}

// ================= k4: KVT[e][d] = sum_l V[l][e]*(alpha*phiK)[l][d] =================
// fp16 2-pass, grid (BHc, KVS=2), 512 threads, 4x4 m32 x n32, softmax folded in.
// PDL: chunk-0 phiK/V prefetched into registers BEFORE griddepcontrol.wait.
#define T_KHI 0
#define T_KLO 16384
#define T_VHI 32768
#define K4_BUF 49152
#define K4_KS  98304
#define K4_ALPHA 106496
#define K4_SMEM (106496 + 8192)

__global__ void __launch_bounds__(512) k4_mma(const float* __restrict__ phiK,
                                              const float* __restrict__ V) {
    extern __shared__ __align__(16) char smem[];
    uint32_t sb = smem_u32(smem);
    int bh = blockIdx.x, s = blockIdx.y;
    int b = bh >> 4, h = bh & 15;
    int t = threadIdx.x, lane = t & 31, w = t >> 5;
    float* alpha_s = (float*)(smem + K4_ALPHA);
    float* red = (float*)(smem + K4_KS);

    const int c4 = lane;
    const int NCH = (Lc / KVS) / 64;   // 32

    float4 kvst[4], vvst[4];

    auto STAGE = [&](int chunk) {   // gmem only (independent of k2)
        int l0 = s * (Lc / KVS) + chunk * 64;
#pragma unroll
        for (int i = 0; i < 4; i++) {
            int lr = w + 16 * i;
            int l = l0 + lr;
            size_t off = ((size_t)(b * Lc + l) * Hc + h) * Dc + c4 * 4;
            kvst[i] = *(const float4*)(phiK + off);
            vvst[i] = *(const float4*)(V + off);
        }
    };

    // ---- PDL prefetch: chunk 0 loads issue while k2 may still be running ----
    STAGE(0);
    GRID_DEP_SYNC();     // k2 complete; g_alpha visible
    GRID_DEP_TRIGGER();  // let k5 launch early and prefetch phiQ

    // ---- prologue: softmax over full L (deterministic, redundant per block) ----
    {
        float v[8];
#pragma unroll
        for (int i = 0; i < 8; i++) v[i] = g_alpha[bh * Lc + t + i * 512];
        float m = v[0];
#pragma unroll
        for (int i = 1; i < 8; i++) m = fmaxf(m, v[i]);
        red[t] = m;
        __syncthreads();
        for (int st = 256; st > 0; st >>= 1) {
            if (t < st) red[t] = fmaxf(red[t], red[t + st]);
            __syncthreads();
        }
        m = red[0];
        __syncthreads();
        float sum = 0.f;
#pragma unroll
        for (int i = 0; i < 8; i++) { v[i] = expf(v[i] - m); sum += v[i]; }
        red[t] = sum;
        __syncthreads();
        for (int st = 256; st > 0; st >>= 1) {
            if (t < st) red[t] += red[t + st];
            __syncthreads();
        }
        float scale = (float)Lc / red[0];
#pragma unroll
        for (int i = 0; i < 4; i++) alpha_s[t + i * 512] = v[s * 4 + i] * scale;
        __syncthreads();
    }

    float acc[8][4];
#pragma unroll
    for (int i = 0; i < 8; i++)
#pragma unroll
        for (int j = 0; j < 4; j++) acc[i][j] = 0.f;
    float4 ksum4 = make_float4(0.f, 0.f, 0.f, 0.f);

    auto CVTST = [&](int buf, int chunk) {
        uint32_t base = (uint32_t)(buf * K4_BUF);
#pragma unroll
        for (int i = 0; i < 4; i++) {
            int lr = w + 16 * i;
            float a = alpha_s[chunk * 64 + lr];
            float4 kv = kvst[i];
            kv.x *= a; kv.y *= a; kv.z *= a; kv.w *= a;
            ksum4.x += kv.x; ksum4.y += kv.y; ksum4.z += kv.z; ksum4.w += kv.w;
            uint32_t wo = lr * 256 + ((((uint32_t)(c4 >> 1)) ^ (lr & 7)) << 4) + (c4 & 1) * 8;
            uint2 hi, lo;
            split4h(kv, hi, lo);
            *(uint2*)(smem + base + T_KHI + wo) = hi;
            *(uint2*)(smem + base + T_KLO + wo) = lo;
            cvt4h(vvst[i], hi);
            *(uint2*)(smem + base + T_VHI + wo) = hi;
        }
    };

    const int ms = w & 3, nh = w >> 2;   // 4x4 warp grid
    const int matj = lane >> 3, rr = lane & 7;
    auto MMA = [&](int buf) {
        uint32_t base = sb + (uint32_t)(buf * K4_BUF);
#pragma unroll
        for (int ks = 0; ks < 4; ks++) {
            int lb = ks * 16;
            uint32_t ah[2][4];
            int lA = lb + (matj >> 1) * 8 + rr;
#pragma unroll
            for (int mi = 0; mi < 2; mi++) {
                int mt = ms * 2 + mi;
                uint32_t aoff = lA * 256 + ((((uint32_t)(mt * 2 + (matj & 1))) ^ (lA & 7)) << 4);
                ldsm_x4_t(ah[mi], base + T_VHI + aoff);
            }
            int lB = lb + (matj & 1) * 8 + rr;
            uint32_t brow = lB * 256;
#pragma unroll
            for (int ni = 0; ni < 2; ni++) {
                int nt = nh * 2 + ni;
                uint32_t boff = brow + ((((uint32_t)(nt * 2 + (matj >> 1))) ^ (lB & 7)) << 4);
                uint32_t bh4[4], bl4[4];
                ldsm_x4_t(bh4, base + T_KHI + boff);
                ldsm_x4_t(bl4, base + T_KLO + boff);
                int a0 = ni * 2, a1 = 4 + ni * 2;
                mma16816h(acc[a0],     ah[0], bh4[0], bh4[1]);
                mma16816h(acc[a0 + 1], ah[0], bh4[2], bh4[3]);
                mma16816h(acc[a1],     ah[1], bh4[0], bh4[1]);
                mma16816h(acc[a1 + 1], ah[1], bh4[2], bh4[3]);
                mma16816h(acc[a0],     ah[0], bl4[0], bl4[1]);
                mma16816h(acc[a0 + 1], ah[0], bl4[2], bl4[3]);
                mma16816h(acc[a1],     ah[1], bl4[0], bl4[1]);
                mma16816h(acc[a1 + 1], ah[1], bl4[2], bl4[3]);
            }
        }
    };

    CVTST(0, 0);
    for (int c = 0; c < NCH; c++) {
        __syncthreads();
        if (c + 1 < NCH) STAGE(c + 1);
        MMA(c & 1);
        if (c + 1 < NCH) CVTST((c + 1) & 1, c + 1);
    }

    __syncthreads();
    *(float4*)(smem + K4_KS + (w * 128 + c4 * 4) * 4) = ksum4;
    __syncthreads();
    if (t < 128) {
        float sum = 0.f;
        const float* ks_s = (const float*)(smem + K4_KS);
#pragma unroll
        for (int g = 0; g < 16; g++) sum += ks_s[g * 128 + t];
        g_ksumpart[(s * BHc + bh) * Dc + t] = sum;
    }

    int r_in = lane >> 2;
    int cc_in = 2 * (lane & 3);
#pragma unroll
    for (int mi = 0; mi < 2; mi++) {
#pragma unroll
        for (int ni = 0; ni < 2; ni++) {
#pragma unroll
            for (int half = 0; half < 2; half++) {
                const float* a = acc[mi * 4 + ni * 2 + half];
                int row = ms * 32 + mi * 16 + r_in;
                int col = nh * 32 + ni * 16 + half * 8 + cc_in;
                float* dst = g_kvpart + (((size_t)s * BHc + bh) * Dc + row) * Dc + col;
                *(float2*)(dst)          = make_float2(a[0], a[1]);
                *(float2*)(dst + 8 * Dc) = make_float2(a[2], a[3]);
            }
        }
    }
}

// ================= k5: out[l][e] = (phiQ_hi @ KVT^T) / (phiQ . ksum + eps) =================
// fp16 2-pass, grid (BHc, 2), 512 threads, warp-specialized (R14 proven config).
// PDL: producer tile-0 phiQ prefetched into registers BEFORE griddepcontrol.wait.
#define K5_BUFS 3
#define K5_BUFSZ 16384
#define K5_GHI 49152
#define K5_GLO 81920
#define K5_DEN 114688
#define K5_KS  115456
#define K5_SMEM (115456 + 512)

__global__ void __launch_bounds__(512) k5_mma(const float* __restrict__ phiQ,
                                              float* __restrict__ out) {
    extern __shared__ __align__(16) char smem[];
    uint32_t sb = smem_u32(smem);
    int bh = blockIdx.x, lt = blockIdx.y;
    int b = bh >> 4, h = bh & 15;
    int l0 = lt * 2048;
    int t = threadIdx.x, lane = t & 31, w = t >> 5;
    float* den_s = (float*)(smem + K5_DEN);
    float* ks_s = (float*)(smem + K5_KS);

    // ---- PDL prefetch: producer warps load tile-0 phiQ (independent of k4) ----
    float4 qst[8];
    if (w >= 8) {
        int pw = w - 8;
#pragma unroll
        for (int i = 0; i < 8; i++) {
            int lr = pw + 8 * i;
            qst[i] = *(const float4*)(phiQ + ((size_t)(b * Lc + l0 + lr) * Hc + h) * Dc + lane * 4);
        }
    }
    GRID_DEP_SYNC();   // k4 complete; g_kvpart / g_ksumpart visible

    // ---- B fill: reduce KVS=2 fp32 partials, split to fp16 hi/lo (all threads) ----
#pragma unroll
    for (int i = 0; i < 8; i++) {
        int seg = t + i * 512;          // 4096 float4 segments
        int e = seg >> 5, dq = seg & 31;
        size_t off = ((size_t)bh * Dc + e) * Dc + dq * 4;
        float4 p0 = *(const float4*)(g_kvpart + off);
        float4 p1 = *(const float4*)(g_kvpart + (size_t)(BHc * Dc) * Dc + off);
        p0.x += p1.x; p0.y += p1.y; p0.z += p1.z; p0.w += p1.w;
        uint2 hi, lo;
        split4h(p0, hi, lo);
        uint32_t wo = e * 256 + ((((uint32_t)(dq >> 1)) ^ (e & 7)) << 4) + (dq & 1) * 8;
        *(uint2*)(smem + K5_GHI + wo) = hi;
        *(uint2*)(smem + K5_GLO + wo) = lo;
    }
    if (t < 128) ks_s[t] = g_ksumpart[bh * Dc + t] + g_ksumpart[BHc * Dc + bh * Dc + t];
    __syncthreads();

    const int NT = 32;   // tiles of 64 l-rows

    if (w >= 8) {
        // ---------------- producer ----------------
        int pw = w - 8;
        const int c4 = lane;
        float4 ksq = *(const float4*)&ks_s[c4 * 4];
        for (int tile = 0; tile < NT; tile++) {
            int buf = tile % K5_BUFS;
            int l0t = l0 + tile * 64;
            if (tile > 0) {
#pragma unroll
                for (int i = 0; i < 8; i++) {
                    int lr = pw + 8 * i;
                    qst[i] = *(const float4*)(phiQ + ((size_t)(b * Lc + l0t + lr) * Hc + h) * Dc + c4 * 4);
                }
            }
            if (tile >= K5_BUFS) BAR_SYNC(4 + buf);
            uint32_t base = (uint32_t)(buf * K5_BUFSZ);
#pragma unroll
            for (int i = 0; i < 8; i++) {
                int lr = pw + 8 * i;
                float4 q = qst[i];
                float part = q.x * ksq.x + q.y * ksq.y + q.z * ksq.z + q.w * ksq.w;
                part += __shfl_xor_sync(0xFFFFFFFFu, part, 16);
                part += __shfl_xor_sync(0xFFFFFFFFu, part, 8);
                part += __shfl_xor_sync(0xFFFFFFFFu, part, 4);
                part += __shfl_xor_sync(0xFFFFFFFFu, part, 2);
                part += __shfl_xor_sync(0xFFFFFFFFu, part, 1);
                if (lane == 0) den_s[buf * 64 + lr] = part;
                uint32_t wo = lr * 256 + ((((uint32_t)(c4 >> 1)) ^ (lr & 7)) << 4) + (c4 & 1) * 8;
                uint2 hi;
                cvt4h(q, hi);
                *(uint2*)(smem + base + wo) = hi;
            }
            BAR_ARRIVE(1 + buf);
        }
    } else {
        // ---------------- consumer ----------------
        const int ms = w & 1, nh = w >> 1;
        const int matj = lane >> 3, rr = lane & 7;
        for (int tile = 0; tile < NT; tile++) {
            int buf = tile % K5_BUFS;
            float acc[8][4];
#pragma unroll
            for (int i = 0; i < 8; i++)
#pragma unroll
                for (int j = 0; j < 4; j++) acc[i][j] = 0.f;
            BAR_SYNC(1 + buf);
            uint32_t abase = sb + (uint32_t)(buf * K5_BUFSZ);
#pragma unroll
            for (int ks = 0; ks < 8; ks++) {
                uint32_t kbA = (uint32_t)(ks * 2 + (matj >> 1));
                uint32_t ah[2][4];
#pragma unroll
                for (int mi = 0; mi < 2; mi++) {
                    int rowA = (ms * 2 + mi) * 16 + (matj & 1) * 8 + rr;
                    uint32_t aoff = rowA * 256 + ((kbA ^ (rowA & 7)) << 4);
                    ldsm_x4(ah[mi], abase + aoff);
                }
                uint32_t kbB = (uint32_t)(ks * 2 + (matj & 1));
#pragma unroll
                for (int np = 0; np < 2; np++) {
                    int nt = nh * 2 + np;
                    int rowB = (nt * 2 + (matj >> 1)) * 8 + rr;
                    uint32_t boff = rowB * 256 + ((kbB ^ (rowB & 7)) << 4);
                    uint32_t bh4[4], bl4[4];
                    ldsm_x4(bh4, sb + K5_GHI + boff);
                    ldsm_x4(bl4, sb + K5_GLO + boff);
                    int a0 = (0 * 2 + np) * 2, a1 = (1 * 2 + np) * 2;
                    mma16816h(acc[a0],     ah[0], bh4[0], bh4[1]);
                    mma16816h(acc[a0 + 1], ah[0], bh4[2], bh4[3]);
                    mma16816h(acc[a1],     ah[1], bh4[0], bh4[1]);
                    mma16816h(acc[a1 + 1], ah[1], bh4[2], bh4[3]);
                    mma16816h(acc[a0],     ah[0], bl4[0], bl4[1]);
                    mma16816h(acc[a0 + 1], ah[0], bl4[2], bl4[3]);
                    mma16816h(acc[a1],     ah[1], bl4[0], bl4[1]);
                    mma16816h(acc[a1 + 1], ah[1], bl4[2], bl4[3]);
                }
            }
            // epilogue (reads den_s before releasing buffer)
            int r_in = lane >> 2;
            int cc_in = 2 * (lane & 3);
            int lb0 = l0 + tile * 64;
#pragma unroll
            for (int mi = 0; mi < 2; mi++) {
                int row = ms * 32 + mi * 16 + r_in;
                float i0 = 1.0f / (den_s[buf * 64 + row] + EPSc);
                float i1 = 1.0f / (den_s[buf * 64 + row + 8] + EPSc);
                float* o0 = out + ((size_t)(b * Lc + lb0 + row) * Hc + h) * Dc;
                float* o1 = o0 + (size_t)8 * Hc * Dc;
#pragma unroll
                for (int np = 0; np < 2; np++) {
#pragma unroll
                    for (int half = 0; half < 2; half++) {
                        const float* a = acc[(mi * 2 + np) * 2 + half];
                        int col = nh * 32 + np * 16 + half * 8 + cc_in;
                        *(float2*)(o0 + col) = make_float2(a[0] * i0, a[1] * i0);
                        *(float2*)(o1 + col) = make_float2(a[2] * i1, a[3] * i1);
                    }
                }
            }
            BAR_ARRIVE(4 + buf);
        }
    }
}

// ================= launcher =================
extern "C" void kernel_launch(void* const* d_in, const int* in_sizes, int n_in,
                              void* d_out, int out_size) {
    const float* Q    = (const float*)d_in[0];
    const float* K    = (const float*)d_in[1];
    const float* V    = (const float*)d_in[2];
    const float* phiQ = (const float*)d_in[3];
    const float* phiK = (const float*)d_in[4];
    float* out = (float*)d_out;

    cudaFuncSetAttribute(k4_mma, cudaFuncAttributeMaxDynamicSharedMemorySize, K4_SMEM);
    cudaFuncSetAttribute(k5_mma, cudaFuncAttributeMaxDynamicSharedMemorySize, K5_SMEM);

    k1_qpart<<<dim3(Bc, SPLITQ), 512>>>(Q);
    k2_scores<<<dim3(BHc, Lc / 256), 256>>>(K);

    cudaLaunchAttribute attrs[1];
    attrs[0].id = cudaLaunchAttributeProgrammaticStreamSerialization;
    attrs[0].val.programmaticStreamSerializationAllowed = 1;

    cudaLaunchConfig_t cfg = {};
    cfg.blockDim = dim3(512, 1, 1);
    cfg.stream = 0;
    cfg.attrs = attrs;
    cfg.numAttrs = 1;

    cfg.gridDim = dim3(BHc, KVS, 1);
    cfg.dynamicSmemBytes = K4_SMEM;
    cudaLaunchKernelEx(&cfg, k4_mma, phiK, V);

    cfg.gridDim = dim3(BHc, 2, 1);
    cfg.dynamicSmemBytes = K5_SMEM;
    cudaLaunchKernelEx(&cfg, k5_mma, phiQ, out);
}